// round 4
// baseline (speedup 1.0000x reference)
#include <cuda_runtime.h>
#include <cstdint>
#include <math.h>

// Problem dims
#define T_TOKENS 2048
#define HDIM     3584
#define IDIM     18944
#define WELEMS   ((long long)IDIM * HDIM)   // 67,895,296 per weight

// ---------------------------------------------------------------------------
// Scratch (device globals: allocation-free per harness rules)
// ---------------------------------------------------------------------------
__device__ __align__(16) int8_t g_qx[(size_t)T_TOKENS * HDIM];
__device__ float               g_sx[T_TOKENS];
__device__ __align__(16) int8_t g_qh[(size_t)T_TOKENS * IDIM];
// repacked int8 weights (gate, up, down)
__device__ __align__(16) int8_t g_w8g[WELEMS];
__device__ __align__(16) int8_t g_w8u[WELEMS];
__device__ __align__(16) int8_t g_w8d[WELEMS];
__device__ int g_is32[3];

// ---------------------------------------------------------------------------
// Helpers
// ---------------------------------------------------------------------------
__device__ __forceinline__ uint32_t smem_u32(const void* p) {
    return (uint32_t)__cvta_generic_to_shared(p);
}
__device__ __forceinline__ void cp16(uint32_t dst, const void* src) {
    asm volatile("cp.async.cg.shared.global [%0], [%1], 16;" :: "r"(dst), "l"(src));
}
__device__ __forceinline__ void cp_commit() {
    asm volatile("cp.async.commit_group;");
}
template <int N>
__device__ __forceinline__ void cp_wait() {
    asm volatile("cp.async.wait_group %0;" :: "n"(N));
}
__device__ __forceinline__ void mma_s8(int* c, const uint32_t* a, uint32_t b0, uint32_t b1) {
    asm volatile(
        "mma.sync.aligned.m16n8k32.row.col.s32.s8.s8.s32 "
        "{%0,%1,%2,%3},{%4,%5,%6,%7},{%8,%9},{%0,%1,%2,%3};"
        : "+r"(c[0]), "+r"(c[1]), "+r"(c[2]), "+r"(c[3])
        : "r"(a[0]), "r"(a[1]), "r"(a[2]), "r"(a[3]), "r"(b0), "r"(b1));
}
__device__ __forceinline__ signed char qsilu(int gi, int ui, float srow,
                                             float gs, float us, float dis) {
    float gv = (float)gi * srow * gs;
    float uv = (float)ui * srow * us;
    float h  = (gv / (1.0f + expf(-gv))) * uv;
    float q  = rintf(h / dis);
    q = fminf(fmaxf(q, -127.0f), 127.0f);
    return (signed char)(int)q;
}

// ---------------------------------------------------------------------------
// Dtype detector: int32-marshaled int8 weights have all |v| <= 127 when read
// as int32. Truly-int8 buffers read as int32 give 4 packed random bytes —
// essentially never all within [-127, 127] for 16 consecutive words.
// Reads 64 bytes per weight: in-bounds under both interpretations.
// ---------------------------------------------------------------------------
__global__ void detect_kernel(const void* w0, const void* w1, const void* w2) {
    if (threadIdx.x == 0 && blockIdx.x == 0) {
        const void* ws[3] = {w0, w1, w2};
        for (int j = 0; j < 3; j++) {
            const int* p = (const int*)ws[j];
            int ok = 1;
            for (int i = 0; i < 16; i++) {
                int v = p[i];
                if (v < -127 || v > 127) ok = 0;
            }
            g_is32[j] = ok;
        }
    }
}

// ---------------------------------------------------------------------------
// Repack: int32 -> int8 (or passthrough copy if already int8)
// ---------------------------------------------------------------------------
__global__ __launch_bounds__(256) void repack_kernel(const void* __restrict__ src,
                                                     int8_t* __restrict__ dst,
                                                     int which) {
    const long long i = ((long long)blockIdx.x * blockDim.x + threadIdx.x) * 4;
    if (i >= WELEMS) return;
    if (g_is32[which]) {
        const int4 v = ((const int4*)src)[i >> 2];
        char4 c;
        c.x = (signed char)v.x; c.y = (signed char)v.y;
        c.z = (signed char)v.z; c.w = (signed char)v.w;
        *(char4*)(dst + i) = c;
    } else {
        *(char4*)(dst + i) = ((const char4*)src)[i >> 2];
    }
}

// ---------------------------------------------------------------------------
// Kernel 0: per-token dynamic int8 quantization of x
// ---------------------------------------------------------------------------
__global__ __launch_bounds__(256) void quant_x_kernel(const float* __restrict__ x) {
    const int row = blockIdx.x;
    const float4* xr = (const float4*)(x + (size_t)row * HDIM);
    const int nv = HDIM / 4;

    float m = 0.0f;
    for (int i = threadIdx.x; i < nv; i += blockDim.x) {
        float4 v = xr[i];
        m = fmaxf(m, fmaxf(fmaxf(fabsf(v.x), fabsf(v.y)), fmaxf(fabsf(v.z), fabsf(v.w))));
    }
    __shared__ float red[32];
    #pragma unroll
    for (int o = 16; o; o >>= 1) m = fmaxf(m, __shfl_xor_sync(0xFFFFFFFFu, m, o));
    if ((threadIdx.x & 31) == 0) red[threadIdx.x >> 5] = m;
    __syncthreads();
    if (threadIdx.x < 32) {
        float v = (threadIdx.x < (blockDim.x >> 5)) ? red[threadIdx.x] : 0.0f;
        #pragma unroll
        for (int o = 16; o; o >>= 1) v = fmaxf(v, __shfl_xor_sync(0xFFFFFFFFu, v, o));
        if (threadIdx.x == 0) red[0] = v;
    }
    __syncthreads();
    const float s = fmaxf(red[0] / 127.0f, 1e-8f);
    if (threadIdx.x == 0) g_sx[row] = s;

    char4* qr = (char4*)(g_qx + (size_t)row * HDIM);
    for (int i = threadIdx.x; i < nv; i += blockDim.x) {
        float4 v = xr[i];
        char4 q;
        q.x = (signed char)(int)fminf(fmaxf(rintf(v.x / s), -127.0f), 127.0f);
        q.y = (signed char)(int)fminf(fmaxf(rintf(v.y / s), -127.0f), 127.0f);
        q.z = (signed char)(int)fminf(fmaxf(rintf(v.z / s), -127.0f), 127.0f);
        q.w = (signed char)(int)fminf(fmaxf(rintf(v.w / s), -127.0f), 127.0f);
        qr[i] = q;
    }
}

// ---------------------------------------------------------------------------
// Kernel 1: fused fc1 — gate & up int8 GEMMs + SwiGLU + requant -> g_qh
// ---------------------------------------------------------------------------
constexpr int SSTR = 80;

__global__ __launch_bounds__(256, 2) void fc1_kernel(
    const float* __restrict__ gsp, const float* __restrict__ usp,
    const float* __restrict__ disp)
{
    __shared__ __align__(16) int8_t sA[2][128 * SSTR];
    __shared__ __align__(16) int8_t sG[2][64 * SSTR];
    __shared__ __align__(16) int8_t sU[2][64 * SSTR];

    const int tid  = threadIdx.x;
    const int warp = tid >> 5, lane = tid & 31;
    const int wm = warp >> 1, wn = warp & 1;
    const int g  = lane >> 2, tg = lane & 3;
    const int m0 = blockIdx.y * 128;
    const int n0 = blockIdx.x * 64;

    const int ar = tid >> 2;
    const int ac = (tid & 3) * 16;

    int accG[2][4][4] = {};
    int accU[2][4][4] = {};

    auto load_stage = [&](int buf, int kt) {
        const int kb = kt * 64;
        #pragma unroll
        for (int j = 0; j < 2; j++) {
            int r = ar + j * 64;
            cp16(smem_u32(&sA[buf][r * SSTR + ac]),
                 g_qx + (size_t)(m0 + r) * HDIM + kb + ac);
        }
        cp16(smem_u32(&sG[buf][ar * SSTR + ac]), g_w8g + (size_t)(n0 + ar) * HDIM + kb + ac);
        cp16(smem_u32(&sU[buf][ar * SSTR + ac]), g_w8u + (size_t)(n0 + ar) * HDIM + kb + ac);
        cp_commit();
    };

    load_stage(0, 0);
    const int KT = HDIM / 64;
    for (int kt = 0; kt < KT; kt++) {
        const int buf = kt & 1;
        if (kt + 1 < KT) { load_stage(buf ^ 1, kt + 1); cp_wait<1>(); }
        else             { cp_wait<0>(); }
        __syncthreads();

        #pragma unroll
        for (int ks = 0; ks < 2; ks++) {
            const int kb = ks * 32 + tg * 4;
            uint32_t a[2][4];
            #pragma unroll
            for (int mt = 0; mt < 2; mt++) {
                const int r = wm * 32 + mt * 16 + g;
                a[mt][0] = *(const uint32_t*)&sA[buf][r * SSTR + kb];
                a[mt][1] = *(const uint32_t*)&sA[buf][(r + 8) * SSTR + kb];
                a[mt][2] = *(const uint32_t*)&sA[buf][r * SSTR + kb + 16];
                a[mt][3] = *(const uint32_t*)&sA[buf][(r + 8) * SSTR + kb + 16];
            }
            #pragma unroll
            for (int nt = 0; nt < 4; nt++) {
                const int cn = wn * 32 + nt * 8 + g;
                const uint32_t b0 = *(const uint32_t*)&sG[buf][cn * SSTR + kb];
                const uint32_t b1 = *(const uint32_t*)&sG[buf][cn * SSTR + kb + 16];
                const uint32_t u0 = *(const uint32_t*)&sU[buf][cn * SSTR + kb];
                const uint32_t u1 = *(const uint32_t*)&sU[buf][cn * SSTR + kb + 16];
                #pragma unroll
                for (int mt = 0; mt < 2; mt++) {
                    mma_s8(accG[mt][nt], a[mt], b0, b1);
                    mma_s8(accU[mt][nt], a[mt], u0, u1);
                }
            }
        }
        __syncthreads();
    }

    const float gscale = *gsp, uscale = *usp, dis = *disp;
    #pragma unroll
    for (int mt = 0; mt < 2; mt++) {
        const int r0 = m0 + wm * 32 + mt * 16 + g;
        const float s0 = g_sx[r0], s1 = g_sx[r0 + 8];
        #pragma unroll
        for (int nt = 0; nt < 4; nt++) {
            const int c = n0 + wn * 32 + nt * 8 + tg * 2;
            char2 v0, v1;
            v0.x = qsilu(accG[mt][nt][0], accU[mt][nt][0], s0, gscale, uscale, dis);
            v0.y = qsilu(accG[mt][nt][1], accU[mt][nt][1], s0, gscale, uscale, dis);
            v1.x = qsilu(accG[mt][nt][2], accU[mt][nt][2], s1, gscale, uscale, dis);
            v1.y = qsilu(accG[mt][nt][3], accU[mt][nt][3], s1, gscale, uscale, dis);
            *(char2*)&g_qh[(size_t)r0 * IDIM + c]       = v0;
            *(char2*)&g_qh[(size_t)(r0 + 8) * IDIM + c] = v1;
        }
    }
}

// ---------------------------------------------------------------------------
// Kernel 2: fc2 (down) — int8 GEMM + fp32 dequant -> out
// ---------------------------------------------------------------------------
__global__ __launch_bounds__(256, 2) void fc2_kernel(
    const float* __restrict__ dsp, const float* __restrict__ disp,
    float* __restrict__ out)
{
    __shared__ __align__(16) int8_t sA[2][128 * SSTR];
    __shared__ __align__(16) int8_t sB[2][128 * SSTR];

    const int tid  = threadIdx.x;
    const int warp = tid >> 5, lane = tid & 31;
    const int wm = warp >> 1, wn = warp & 1;
    const int g  = lane >> 2, tg = lane & 3;
    const int m0 = blockIdx.y * 128;
    const int n0 = blockIdx.x * 128;

    const int ar = tid >> 2;
    const int ac = (tid & 3) * 16;

    int acc[2][8][4] = {};

    auto load_stage = [&](int buf, int kt) {
        const int kb = kt * 64;
        #pragma unroll
        for (int j = 0; j < 2; j++) {
            const int r = ar + j * 64;
            cp16(smem_u32(&sA[buf][r * SSTR + ac]),
                 g_qh + (size_t)(m0 + r) * IDIM + kb + ac);
            cp16(smem_u32(&sB[buf][r * SSTR + ac]),
                 g_w8d + (size_t)(n0 + r) * IDIM + kb + ac);
        }
        cp_commit();
    };

    load_stage(0, 0);
    const int KT = IDIM / 64;
    for (int kt = 0; kt < KT; kt++) {
        const int buf = kt & 1;
        if (kt + 1 < KT) { load_stage(buf ^ 1, kt + 1); cp_wait<1>(); }
        else             { cp_wait<0>(); }
        __syncthreads();

        #pragma unroll
        for (int ks = 0; ks < 2; ks++) {
            const int kb = ks * 32 + tg * 4;
            uint32_t a[2][4];
            #pragma unroll
            for (int mt = 0; mt < 2; mt++) {
                const int r = wm * 32 + mt * 16 + g;
                a[mt][0] = *(const uint32_t*)&sA[buf][r * SSTR + kb];
                a[mt][1] = *(const uint32_t*)&sA[buf][(r + 8) * SSTR + kb];
                a[mt][2] = *(const uint32_t*)&sA[buf][r * SSTR + kb + 16];
                a[mt][3] = *(const uint32_t*)&sA[buf][(r + 8) * SSTR + kb + 16];
            }
            #pragma unroll
            for (int nt = 0; nt < 8; nt++) {
                const int cn = wn * 64 + nt * 8 + g;
                const uint32_t b0 = *(const uint32_t*)&sB[buf][cn * SSTR + kb];
                const uint32_t b1 = *(const uint32_t*)&sB[buf][cn * SSTR + kb + 16];
                #pragma unroll
                for (int mt = 0; mt < 2; mt++) {
                    mma_s8(acc[mt][nt], a[mt], b0, b1);
                }
            }
        }
        __syncthreads();
    }

    const float oscale = (*disp) * (*dsp);
    #pragma unroll
    for (int mt = 0; mt < 2; mt++) {
        const int r0 = m0 + wm * 32 + mt * 16 + g;
        #pragma unroll
        for (int nt = 0; nt < 8; nt++) {
            const int c = n0 + wn * 64 + nt * 8 + tg * 2;
            float2 v0, v1;
            v0.x = (float)acc[mt][nt][0] * oscale;
            v0.y = (float)acc[mt][nt][1] * oscale;
            v1.x = (float)acc[mt][nt][2] * oscale;
            v1.y = (float)acc[mt][nt][3] * oscale;
            *(float2*)&out[(size_t)r0 * HDIM + c]       = v0;
            *(float2*)&out[(size_t)(r0 + 8) * HDIM + c] = v1;
        }
    }
}

// ---------------------------------------------------------------------------
// Entry point
// ---------------------------------------------------------------------------
extern "C" void kernel_launch(void* const* d_in, const int* in_sizes, int n_in,
                              void* d_out, int out_size) {
    const int XSZ = T_TOKENS * HDIM;

    int xi = -1, widx[3] = {-1,-1,-1}, sidx[4] = {-1,-1,-1,-1};
    int nw = 0, ns = 0;
    for (int i = 0; i < n_in; i++) {
        if (in_sizes[i] == XSZ) xi = i;
        else if ((long long)in_sizes[i] == WELEMS) { if (nw < 3) widx[nw++] = i; }
        else if (in_sizes[i] == 1) { if (ns < 4) sidx[ns++] = i; }
    }

    const float *x, *gs, *us, *ds, *dis;
    const void *gw, *uw, *dw;

    if (xi == 0) {
        // dict order: x, gate_w, up_w, down_w, gate_w_scale, up_w_scale,
        //             down_w_scale, down_input_scale
        x   = (const float*)d_in[xi];
        gw  = d_in[widx[0]];
        uw  = d_in[widx[1]];
        dw  = d_in[widx[2]];
        gs  = (const float*)d_in[sidx[0]];
        us  = (const float*)d_in[sidx[1]];
        ds  = (const float*)d_in[sidx[2]];
        dis = (const float*)d_in[sidx[3]];
    } else {
        // alphabetical fallback
        x   = (const float*)d_in[xi];
        dw  = d_in[widx[0]];
        gw  = d_in[widx[1]];
        uw  = d_in[widx[2]];
        dis = (const float*)d_in[sidx[0]];
        ds  = (const float*)d_in[sidx[1]];
        gs  = (const float*)d_in[sidx[2]];
        us  = (const float*)d_in[sidx[3]];
    }

    float* out = (float*)d_out;

    detect_kernel<<<1, 32>>>(gw, uw, dw);

    const int rp_blocks = (int)((WELEMS / 4 + 255) / 256);
    int8_t* w8g; cudaGetSymbolAddress((void**)&w8g, g_w8g);
    int8_t* w8u; cudaGetSymbolAddress((void**)&w8u, g_w8u);
    int8_t* w8d; cudaGetSymbolAddress((void**)&w8d, g_w8d);
    repack_kernel<<<rp_blocks, 256>>>(gw, w8g, 0);
    repack_kernel<<<rp_blocks, 256>>>(uw, w8u, 1);
    repack_kernel<<<rp_blocks, 256>>>(dw, w8d, 2);

    quant_x_kernel<<<T_TOKENS, 256>>>(x);
    fc1_kernel<<<dim3(IDIM / 64, T_TOKENS / 128), 256>>>(gs, us, dis);
    fc2_kernel<<<dim3(HDIM / 128, T_TOKENS / 128), 256>>>(ds, dis, out);
}

// round 6
// speedup vs baseline: 1.0472x; 1.0472x over previous
#include <cuda_runtime.h>
#include <cstdint>
#include <math.h>

// Problem dims
#define T_TOKENS 2048
#define HDIM     3584
#define IDIM     18944
#define WELEMS   ((long long)IDIM * HDIM)

// ---------------------------------------------------------------------------
// Scratch (device globals)
// ---------------------------------------------------------------------------
__device__ __align__(16) int8_t g_qx[(size_t)T_TOKENS * HDIM];
__device__ float               g_sx[T_TOKENS];
__device__ __align__(16) int8_t g_qh[(size_t)T_TOKENS * IDIM];
__device__ __align__(16) int8_t g_w8g[WELEMS];
__device__ __align__(16) int8_t g_w8u[WELEMS];
__device__ __align__(16) int8_t g_w8d[WELEMS];
__device__ int g_is32[3];

// ---------------------------------------------------------------------------
// Helpers
// ---------------------------------------------------------------------------
__device__ __forceinline__ uint32_t smem_u32(const void* p) {
    return (uint32_t)__cvta_generic_to_shared(p);
}
__device__ __forceinline__ void cp16(uint32_t dst, const void* src) {
    asm volatile("cp.async.cg.shared.global [%0], [%1], 16;" :: "r"(dst), "l"(src));
}
__device__ __forceinline__ void cp_commit() {
    asm volatile("cp.async.commit_group;");
}
template <int N>
__device__ __forceinline__ void cp_wait() {
    asm volatile("cp.async.wait_group %0;" :: "n"(N));
}
// ldmatrix x4: 4 8x(16B) matrices; lane l of quad q supplies the row address.
__device__ __forceinline__ void ldsm_x4(uint32_t* r, uint32_t saddr) {
    asm volatile("ldmatrix.sync.aligned.m8n8.x4.shared.b16 {%0,%1,%2,%3}, [%4];"
                 : "=r"(r[0]), "=r"(r[1]), "=r"(r[2]), "=r"(r[3]) : "r"(saddr));
}
__device__ __forceinline__ void mma_s8(int* c, const uint32_t* a, uint32_t b0, uint32_t b1) {
    asm volatile(
        "mma.sync.aligned.m16n8k32.row.col.s32.s8.s8.s32 "
        "{%0,%1,%2,%3},{%4,%5,%6,%7},{%8,%9},{%0,%1,%2,%3};"
        : "+r"(c[0]), "+r"(c[1]), "+r"(c[2]), "+r"(c[3])
        : "r"(a[0]), "r"(a[1]), "r"(a[2]), "r"(a[3]), "r"(b0), "r"(b1));
}
__device__ __forceinline__ signed char qsilu(int gi, int ui, float srow,
                                             float gs, float us, float dis) {
    float gv = (float)gi * srow * gs;
    float uv = (float)ui * srow * us;
    float h  = (gv / (1.0f + expf(-gv))) * uv;
    float q  = rintf(h / dis);
    q = fminf(fmaxf(q, -127.0f), 127.0f);
    return (signed char)(int)q;
}

constexpr int SSTR = 80;      // padded smem row stride (conflict-free for LDSM)
constexpr int NSTG = 4;       // ring buffers (3-deep pipeline)
#define FC_STG   20480        // stage bytes (fc1: A 10240 + G 5120 + U 5120; fc2: A+B 10240 each)
#define FC_SMEM  (NSTG * FC_STG)

// ---------------------------------------------------------------------------
// Dtype detector + repack (proven in R4)
// ---------------------------------------------------------------------------
__global__ void detect_kernel(const void* w0, const void* w1, const void* w2) {
    if (threadIdx.x == 0 && blockIdx.x == 0) {
        const void* ws[3] = {w0, w1, w2};
        for (int j = 0; j < 3; j++) {
            const int* p = (const int*)ws[j];
            int ok = 1;
            for (int i = 0; i < 16; i++) {
                int v = p[i];
                if (v < -127 || v > 127) ok = 0;
            }
            g_is32[j] = ok;
        }
    }
}

__global__ __launch_bounds__(256) void repack_kernel(const void* __restrict__ src,
                                                     int8_t* __restrict__ dst,
                                                     int which) {
    const long long i = ((long long)blockIdx.x * blockDim.x + threadIdx.x) * 4;
    if (i >= WELEMS) return;
    if (g_is32[which]) {
        const int4 v = ((const int4*)src)[i >> 2];
        char4 c;
        c.x = (signed char)v.x; c.y = (signed char)v.y;
        c.z = (signed char)v.z; c.w = (signed char)v.w;
        *(char4*)(dst + i) = c;
    } else {
        *(char4*)(dst + i) = ((const char4*)src)[i >> 2];
    }
}

// ---------------------------------------------------------------------------
// Kernel 0: per-token dynamic int8 quantization of x (proven in R4)
// ---------------------------------------------------------------------------
__global__ __launch_bounds__(256) void quant_x_kernel(const float* __restrict__ x) {
    const int row = blockIdx.x;
    const float4* xr = (const float4*)(x + (size_t)row * HDIM);
    const int nv = HDIM / 4;

    float m = 0.0f;
    for (int i = threadIdx.x; i < nv; i += blockDim.x) {
        float4 v = xr[i];
        m = fmaxf(m, fmaxf(fmaxf(fabsf(v.x), fabsf(v.y)), fmaxf(fabsf(v.z), fabsf(v.w))));
    }
    __shared__ float red[32];
    #pragma unroll
    for (int o = 16; o; o >>= 1) m = fmaxf(m, __shfl_xor_sync(0xFFFFFFFFu, m, o));
    if ((threadIdx.x & 31) == 0) red[threadIdx.x >> 5] = m;
    __syncthreads();
    if (threadIdx.x < 32) {
        float v = (threadIdx.x < (blockDim.x >> 5)) ? red[threadIdx.x] : 0.0f;
        #pragma unroll
        for (int o = 16; o; o >>= 1) v = fmaxf(v, __shfl_xor_sync(0xFFFFFFFFu, v, o));
        if (threadIdx.x == 0) red[0] = v;
    }
    __syncthreads();
    const float s = fmaxf(red[0] / 127.0f, 1e-8f);
    if (threadIdx.x == 0) g_sx[row] = s;

    char4* qr = (char4*)(g_qx + (size_t)row * HDIM);
    for (int i = threadIdx.x; i < nv; i += blockDim.x) {
        float4 v = xr[i];
        char4 q;
        q.x = (signed char)(int)fminf(fmaxf(rintf(v.x / s), -127.0f), 127.0f);
        q.y = (signed char)(int)fminf(fmaxf(rintf(v.y / s), -127.0f), 127.0f);
        q.z = (signed char)(int)fminf(fmaxf(rintf(v.z / s), -127.0f), 127.0f);
        q.w = (signed char)(int)fminf(fmaxf(rintf(v.w / s), -127.0f), 127.0f);
        qr[i] = q;
    }
}

// ---------------------------------------------------------------------------
// fc1: BM=128, BN=64 dual (gate+up), BK=64, 8 warps (4m x 2n), warp 32x32/gemm
// 3-deep cp.async pipeline over 4 buffers, LDSM fragment loads.
// stage layout: A [0,10240), G [10240,15360), U [15360,20480)
// ---------------------------------------------------------------------------
__global__ __launch_bounds__(256, 2) void fc1_kernel(
    const float* __restrict__ gsp, const float* __restrict__ usp,
    const float* __restrict__ disp)
{
    extern __shared__ __align__(128) int8_t smem[];
    const uint32_t sb = smem_u32(smem);

    const int tid  = threadIdx.x;
    const int warp = tid >> 5, lane = tid & 31;
    const int wm = warp >> 1, wn = warp & 1;
    const int g  = lane >> 2, tg = lane & 3;
    const int m0 = blockIdx.x * 128;       // M fastest -> weight L2 reuse
    const int n0 = blockIdx.y * 64;

    // lane-invariant LDSM offsets (bytes)
    const uint32_t aoff = (uint32_t)(((lane & 7) + ((lane >> 3) & 1) * 8) * SSTR + (lane >> 4) * 16);
    const uint32_t boff = (uint32_t)(((lane & 7) + (lane >> 4) * 8) * SSTR + ((lane >> 3) & 1) * 16);

    // cp.async load positions
    const int a_r0 = tid >> 1;                 // with i*? below
    const int w_r  = tid >> 2;                 // 0..63
    const int w_c  = (tid & 3) * 16;

    int accG[2][4][4] = {};
    int accU[2][4][4] = {};

    auto load_stage = [&](int s) {
        const uint32_t base = sb + (uint32_t)(s & 3) * FC_STG;
        const int kb = s * 64;
        // A: 128 rows x 64B -> 512 cp16, 2 per thread
        #pragma unroll
        for (int i = 0; i < 2; i++) {
            const int idx = tid + i * 256;
            const int r = idx >> 2, c = (idx & 3) * 16;
            cp16(base + r * SSTR + c, g_qx + (size_t)(m0 + r) * HDIM + kb + c);
        }
        // G, U: 64 rows x 64B -> 256 cp16 each, 1 per thread
        cp16(base + 10240 + w_r * SSTR + w_c, g_w8g + (size_t)(n0 + w_r) * HDIM + kb + w_c);
        cp16(base + 15360 + w_r * SSTR + w_c, g_w8u + (size_t)(n0 + w_r) * HDIM + kb + w_c);
    };

    const int S = HDIM / 64;  // 56
    load_stage(0); cp_commit();
    load_stage(1); cp_commit();
    load_stage(2); cp_commit();

    for (int s = 0; s < S; s++) {
        cp_wait<2>();
        __syncthreads();
        if (s + 3 < S) load_stage(s + 3);
        cp_commit();   // empty group when past the end keeps wait-count exact

        const uint32_t base = sb + (uint32_t)(s & 3) * FC_STG;
        const uint32_t abase = base + (uint32_t)(wm * 32) * SSTR + aoff;
        const uint32_t gbase = base + 10240 + (uint32_t)(wn * 32) * SSTR + boff;
        const uint32_t ubase = base + 15360 + (uint32_t)(wn * 32) * SSTR + boff;

        #pragma unroll
        for (int ks = 0; ks < 2; ks++) {
            uint32_t a[2][4];
            ldsm_x4(a[0], abase + ks * 32);
            ldsm_x4(a[1], abase + 16 * SSTR + ks * 32);
            #pragma unroll
            for (int p = 0; p < 2; p++) {
                uint32_t bg[4], bu[4];
                ldsm_x4(bg, gbase + p * 16 * SSTR + ks * 32);
                ldsm_x4(bu, ubase + p * 16 * SSTR + ks * 32);
                #pragma unroll
                for (int mt = 0; mt < 2; mt++) {
                    mma_s8(accG[mt][2 * p],     a[mt], bg[0], bg[1]);
                    mma_s8(accG[mt][2 * p + 1], a[mt], bg[2], bg[3]);
                    mma_s8(accU[mt][2 * p],     a[mt], bu[0], bu[1]);
                    mma_s8(accU[mt][2 * p + 1], a[mt], bu[2], bu[3]);
                }
            }
        }
    }

    const float gscale = *gsp, uscale = *usp, dis = *disp;
    #pragma unroll
    for (int mt = 0; mt < 2; mt++) {
        const int r0 = m0 + wm * 32 + mt * 16 + g;
        const float s0 = g_sx[r0], s1 = g_sx[r0 + 8];
        #pragma unroll
        for (int nt = 0; nt < 4; nt++) {
            const int c = n0 + wn * 32 + nt * 8 + tg * 2;
            char2 v0, v1;
            v0.x = qsilu(accG[mt][nt][0], accU[mt][nt][0], s0, gscale, uscale, dis);
            v0.y = qsilu(accG[mt][nt][1], accU[mt][nt][1], s0, gscale, uscale, dis);
            v1.x = qsilu(accG[mt][nt][2], accU[mt][nt][2], s1, gscale, uscale, dis);
            v1.y = qsilu(accG[mt][nt][3], accU[mt][nt][3], s1, gscale, uscale, dis);
            *(char2*)&g_qh[(size_t)r0 * IDIM + c]       = v0;
            *(char2*)&g_qh[(size_t)(r0 + 8) * IDIM + c] = v1;
        }
    }
}

// ---------------------------------------------------------------------------
// fc2: BM=128, BN=128, BK=64, 8 warps (4m x 2n), warp 32x64
// stage layout: A [0,10240), B [10240,20480)
// ---------------------------------------------------------------------------
__global__ __launch_bounds__(256, 2) void fc2_kernel(
    const float* __restrict__ dsp, const float* __restrict__ disp,
    float* __restrict__ out)
{
    extern __shared__ __align__(128) int8_t smem[];
    const uint32_t sb = smem_u32(smem);

    const int tid  = threadIdx.x;
    const int warp = tid >> 5, lane = tid & 31;
    const int wm = warp >> 1, wn = warp & 1;
    const int g  = lane >> 2, tg = lane & 3;
    const int m0 = blockIdx.x * 128;
    const int n0 = blockIdx.y * 128;

    const uint32_t aoff = (uint32_t)(((lane & 7) + ((lane >> 3) & 1) * 8) * SSTR + (lane >> 4) * 16);
    const uint32_t boff = (uint32_t)(((lane & 7) + (lane >> 4) * 8) * SSTR + ((lane >> 3) & 1) * 16);

    int acc[2][8][4] = {};

    auto load_stage = [&](int s) {
        const uint32_t base = sb + (uint32_t)(s & 3) * FC_STG;
        const int kb = s * 64;
        #pragma unroll
        for (int i = 0; i < 2; i++) {
            const int idx = tid + i * 256;
            const int r = idx >> 2, c = (idx & 3) * 16;
            cp16(base + r * SSTR + c,         g_qh  + (size_t)(m0 + r) * IDIM + kb + c);
            cp16(base + 10240 + r * SSTR + c, g_w8d + (size_t)(n0 + r) * IDIM + kb + c);
        }
    };

    const int S = IDIM / 64;  // 296
    load_stage(0); cp_commit();
    load_stage(1); cp_commit();
    load_stage(2); cp_commit();

    for (int s = 0; s < S; s++) {
        cp_wait<2>();
        __syncthreads();
        if (s + 3 < S) load_stage(s + 3);
        cp_commit();

        const uint32_t base = sb + (uint32_t)(s & 3) * FC_STG;
        const uint32_t abase = base + (uint32_t)(wm * 32) * SSTR + aoff;
        const uint32_t bbase = base + 10240 + (uint32_t)(wn * 64) * SSTR + boff;

        #pragma unroll
        for (int ks = 0; ks < 2; ks++) {
            uint32_t a[2][4];
            ldsm_x4(a[0], abase + ks * 32);
            ldsm_x4(a[1], abase + 16 * SSTR + ks * 32);
            #pragma unroll
            for (int p = 0; p < 4; p++) {
                uint32_t bb[4];
                ldsm_x4(bb, bbase + p * 16 * SSTR + ks * 32);
                #pragma unroll
                for (int mt = 0; mt < 2; mt++) {
                    mma_s8(acc[mt][2 * p],     a[mt], bb[0], bb[1]);
                    mma_s8(acc[mt][2 * p + 1], a[mt], bb[2], bb[3]);
                }
            }
        }
    }

    const float oscale = (*disp) * (*dsp);
    #pragma unroll
    for (int mt = 0; mt < 2; mt++) {
        const int r0 = m0 + wm * 32 + mt * 16 + g;
        #pragma unroll
        for (int nt = 0; nt < 8; nt++) {
            const int c = n0 + wn * 64 + nt * 8 + tg * 2;
            float2 v0, v1;
            v0.x = (float)acc[mt][nt][0] * oscale;
            v0.y = (float)acc[mt][nt][1] * oscale;
            v1.x = (float)acc[mt][nt][2] * oscale;
            v1.y = (float)acc[mt][nt][3] * oscale;
            *(float2*)&out[(size_t)r0 * HDIM + c]       = v0;
            *(float2*)&out[(size_t)(r0 + 8) * HDIM + c] = v1;
        }
    }
}

// ---------------------------------------------------------------------------
// Entry point
// ---------------------------------------------------------------------------
extern "C" void kernel_launch(void* const* d_in, const int* in_sizes, int n_in,
                              void* d_out, int out_size) {
    const int XSZ = T_TOKENS * HDIM;

    int xi = -1, widx[3] = {-1,-1,-1}, sidx[4] = {-1,-1,-1,-1};
    int nw = 0, ns = 0;
    for (int i = 0; i < n_in; i++) {
        if (in_sizes[i] == XSZ) xi = i;
        else if ((long long)in_sizes[i] == WELEMS) { if (nw < 3) widx[nw++] = i; }
        else if (in_sizes[i] == 1) { if (ns < 4) sidx[ns++] = i; }
    }

    const float *x, *gs, *us, *ds, *dis;
    const void *gw, *uw, *dw;

    if (xi == 0) {
        x   = (const float*)d_in[xi];
        gw  = d_in[widx[0]];
        uw  = d_in[widx[1]];
        dw  = d_in[widx[2]];
        gs  = (const float*)d_in[sidx[0]];
        us  = (const float*)d_in[sidx[1]];
        ds  = (const float*)d_in[sidx[2]];
        dis = (const float*)d_in[sidx[3]];
    } else {
        x   = (const float*)d_in[xi];
        dw  = d_in[widx[0]];
        gw  = d_in[widx[1]];
        uw  = d_in[widx[2]];
        dis = (const float*)d_in[sidx[0]];
        ds  = (const float*)d_in[sidx[1]];
        gs  = (const float*)d_in[sidx[2]];
        us  = (const float*)d_in[sidx[3]];
    }

    float* out = (float*)d_out;

    static int smem_set = 0;
    if (!smem_set) {
        cudaFuncSetAttribute(fc1_kernel, cudaFuncAttributeMaxDynamicSharedMemorySize, FC_SMEM);
        cudaFuncSetAttribute(fc2_kernel, cudaFuncAttributeMaxDynamicSharedMemorySize, FC_SMEM);
        smem_set = 1;
    }

    detect_kernel<<<1, 32>>>(gw, uw, dw);

    const int rp_blocks = (int)((WELEMS / 4 + 255) / 256);
    int8_t* w8g; cudaGetSymbolAddress((void**)&w8g, g_w8g);
    int8_t* w8u; cudaGetSymbolAddress((void**)&w8u, g_w8u);
    int8_t* w8d; cudaGetSymbolAddress((void**)&w8d, g_w8d);
    repack_kernel<<<rp_blocks, 256>>>(gw, w8g, 0);
    repack_kernel<<<rp_blocks, 256>>>(uw, w8u, 1);
    repack_kernel<<<rp_blocks, 256>>>(dw, w8d, 2);

    quant_x_kernel<<<T_TOKENS, 256>>>(x);

    // M fastest (grid.x) so concurrent CTAs share weight stripes in L2.
    fc1_kernel<<<dim3(T_TOKENS / 128, IDIM / 64), 256, FC_SMEM>>>(gs, us, dis);
    fc2_kernel<<<dim3(T_TOKENS / 128, HDIM / 128), 256, FC_SMEM>>>(ds, dis, out);
}